// round 4
// baseline (speedup 1.0000x reference)
#include <cuda_runtime.h>

// FocusModules: stage1 window pruning + stage3 adjacent merge.
// x: [N, 256] f32.  out (float32): [ mask1 (N) | compressed (N*256) ].
//
// One CTA (512 thr, 16 warps) per 32-token window; each warp owns 2 tokens.
// mean_sim[i] = dot(xn_i, sum_j xn_j)/32 = inv_i * dot(raw_i, s)/32,
// where s[c] = sum_r raw[r][c]*inv_r  (avoids the 32x32 sim matrix).
//
// Targeting 4 CTAs/SM (full occupancy): rows are staged in smem and reloaded
// per-phase so register liveness stays under the 32-reg budget.

#define DIMV 64          // float4 per token (256 floats)
#define WTOK 32          // window size

__device__ __forceinline__ float warp_sum(float v) {
    #pragma unroll
    for (int o = 16; o; o >>= 1) v += __shfl_xor_sync(0xFFFFFFFFu, v, o);
    return v;
}

__device__ __forceinline__ float dot4(float4 a, float4 b) {
    return a.x * b.x + a.y * b.y + a.z * b.z + a.w * b.w;
}

__global__ void __launch_bounds__(512, 4)
focus_kernel(const float4* __restrict__ x,
             float* __restrict__ mask_out,        // N floats (0/1)
             float4* __restrict__ comp_out)       // N*64 float4
{
    // Raw token rows: 0..31 = window tokens, 32 = previous window's last token.
    __shared__ float4 xs[33][DIMV];                  // 33 KB, 16B aligned
    __shared__ __align__(16) float s_s[256];         // weighted column sums
    __shared__ float  inv_s[33];                     // per-row 1/||x||
    __shared__ float  ms_s[WTOK];                    // per-token mean similarity

    const int w    = blockIdx.x;
    const int warp = threadIdx.x >> 5;
    const int lane = threadIdx.x & 31;
    const int t0   = w * WTOK;
    const int tA   = 2 * warp;           // local token ids for this warp
    const int tB   = 2 * warp + 1;

    // ---- Phase A: load 2 tokens, compute norms, stage raw into smem ----
    {
        const float4* xa = x + (size_t)(t0 + tA) * DIMV;
        const float4* xb = x + (size_t)(t0 + tB) * DIMV;
        const float4 a0 = __ldcs(xa + lane), a1 = __ldcs(xa + 32 + lane);
        const float4 b0 = __ldcs(xb + lane), b1 = __ldcs(xb + 32 + lane);

        float sa = dot4(a0, a0) + dot4(a1, a1);
        float sb = dot4(b0, b0) + dot4(b1, b1);
        #pragma unroll
        for (int o = 16; o; o >>= 1) {
            sa += __shfl_xor_sync(0xFFFFFFFFu, sa, o);
            sb += __shfl_xor_sync(0xFFFFFFFFu, sb, o);
        }
        xs[tA][lane] = a0;  xs[tA][32 + lane] = a1;
        xs[tB][lane] = b0;  xs[tB][32 + lane] = b1;
        if (lane == 0) {
            inv_s[tA] = 1.0f / fmaxf(sqrtf(sa), 1e-12f);
            inv_s[tB] = 1.0f / fmaxf(sqrtf(sb), 1e-12f);
        }
        // warp 0 stages the previous window's last token into row 32
        if (warp == 0 && w > 0) {
            const float4* xp = x + (size_t)(t0 - 1) * DIMV;
            float4 p0 = xp[lane], p1 = xp[32 + lane];
            float sp = warp_sum(dot4(p0, p0) + dot4(p1, p1));
            xs[32][lane] = p0;  xs[32][32 + lane] = p1;
            if (lane == 0) inv_s[32] = 1.0f / fmaxf(sqrtf(sp), 1e-12f);
        }
    }
    __syncthreads();

    // ---- Phase C1: adjacent dots + stage-3 mask + compressed stores (early) ----
    {
        const float4 z = make_float4(0.f, 0.f, 0.f, 0.f);
        const int prow = (tA == 0) ? 32 : (tA - 1);

        // token A (partner row dies before token B's rows load -> low liveness)
        float4 a0 = xs[tA][lane], a1 = xs[tA][32 + lane];
        {
            float4 p0 = xs[prow][lane], p1 = xs[prow][32 + lane];
            float dA = warp_sum(dot4(a0, p0) + dot4(a1, p1));
            bool m3 = (t0 + tA == 0) || (inv_s[tA] * inv_s[prow] * dA < 0.7f);
            float4* dst = comp_out + (size_t)(t0 + tA) * DIMV;
            __stcs(dst + lane,      m3 ? a0 : z);
            __stcs(dst + 32 + lane, m3 ? a1 : z);
        }
        // token B (partner is token A, already in regs)
        {
            float4 b0 = xs[tB][lane], b1 = xs[tB][32 + lane];
            float dB = warp_sum(dot4(b0, a0) + dot4(b1, a1));
            bool m3 = (inv_s[tB] * inv_s[tA] * dB < 0.7f);
            float4* dst = comp_out + (size_t)(t0 + tB) * DIMV;
            __stcs(dst + lane,      m3 ? b0 : z);
            __stcs(dst + 32 + lane, m3 ? b1 : z);
        }
    }

    // ---- Phase B: weighted column sums (normalized-token column sums) ----
    if (threadIdx.x < 256) {
        const float* base = (const float*)xs;   // row stride = 256 floats
        const int c = threadIdx.x;
        float acc = 0.0f;
        #pragma unroll
        for (int r = 0; r < WTOK; r++) acc += base[r * 256 + c] * inv_s[r];
        s_s[c] = acc;
    }
    __syncthreads();

    // ---- Phase C2: mean-similarity dots ----
    {
        const float4* sv = (const float4*)s_s;
        const float4 s0 = sv[lane];
        const float4 s1 = sv[32 + lane];
        float4 a0 = xs[tA][lane], a1 = xs[tA][32 + lane];
        float4 b0 = xs[tB][lane], b1 = xs[tB][32 + lane];
        float dA = dot4(a0, s0) + dot4(a1, s1);
        float dB = dot4(b0, s0) + dot4(b1, s1);
        #pragma unroll
        for (int o = 16; o; o >>= 1) {
            dA += __shfl_xor_sync(0xFFFFFFFFu, dA, o);
            dB += __shfl_xor_sync(0xFFFFFFFFu, dB, o);
        }
        if (lane == 0) {
            ms_s[tA] = inv_s[tA] * dA * (1.0f / 32.0f);
            ms_s[tB] = inv_s[tB] * dB * (1.0f / 32.0f);
        }
    }
    __syncthreads();

    // ---- Phase D: window statistics + stage-1 mask (warp 0 only) ----
    if (warp == 0) {
        const float m = ms_s[lane];
        float mu = warp_sum(m) * (1.0f / 32.0f);
        float d = m - mu;
        float var = warp_sum(d * d) * (1.0f / 31.0f);   // ddof=1
        float sd = sqrtf(var);
        bool keep = !(m > mu + sd);
        unsigned bal = __ballot_sync(0xFFFFFFFFu, keep);
        if (bal == 0u) {
            // fallback: keep argmin(mean_sim), first index on ties
            float bv = m; int bi = lane;
            #pragma unroll
            for (int o = 16; o; o >>= 1) {
                float ov = __shfl_xor_sync(0xFFFFFFFFu, bv, o);
                int   oi = __shfl_xor_sync(0xFFFFFFFFu, bi, o);
                if (ov < bv || (ov == bv && oi < bi)) { bv = ov; bi = oi; }
            }
            keep = (lane == bi);
        }
        mask_out[t0 + lane] = keep ? 1.0f : 0.0f;
    }
}

extern "C" void kernel_launch(void* const* d_in, const int* in_sizes, int n_in,
                              void* d_out, int out_size)
{
    const float4* x = (const float4*)d_in[0];
    const int N = in_sizes[0] / 256;       // tokens
    const int nwin = N / WTOK;             // windows

    float* out = (float*)d_out;
    float*  mask_out = out;                // first N floats
    float4* comp_out = (float4*)(out + N); // N multiple of 4 -> 16B aligned

    focus_kernel<<<nwin, 512>>>(x, mask_out, comp_out);
}

// round 5
// speedup vs baseline: 1.0316x; 1.0316x over previous
#include <cuda_runtime.h>
#include <cstdint>

// FocusModules via TMA bulk copies: stage1 window pruning + stage3 adjacent merge.
// x: [N, 256] f32.  out (float32): [ mask1 (N) | compressed (N*256) ].
//
// One CTA (512 thr, 16 warps) per 32-token window.
// tile row r (r=0..32) = global token t0-1+r  (row 0 = prev window's last token).
// mean_sim[i] = inv_i * dot(raw_i, s)/32, s[c] = sum_r raw[r][c]*inv_r.
// Bulk-load 33KB in, compute from smem/regs, zero masked rows in place,
// bulk-store 32KB out. Streaming traffic stays off the L1tex pipe.

#define WTOK 32

__device__ __forceinline__ uint32_t smem_u32(const void* p) {
    return (uint32_t)__cvta_generic_to_shared(p);
}
__device__ __forceinline__ float warp_sum(float v) {
    #pragma unroll
    for (int o = 16; o; o >>= 1) v += __shfl_xor_sync(0xFFFFFFFFu, v, o);
    return v;
}
__device__ __forceinline__ float dot4(float4 a, float4 b) {
    return a.x * b.x + a.y * b.y + a.z * b.z + a.w * b.w;
}

__global__ void __launch_bounds__(512, 3)
focus_kernel(const float* __restrict__ x,
             float* __restrict__ mask_out,        // N floats (0/1)
             float* __restrict__ comp_out)        // N*256 floats
{
    __shared__ __align__(128) float tile[33 * 256];   // 33 KB
    __shared__ __align__(16)  float s_s[256];         // weighted column sums
    __shared__ float inv_s[33];                       // per-row 1/||x||
    __shared__ float ms_s[WTOK];                      // per-token mean similarity
    __shared__ __align__(8) unsigned long long mbar;

    const int w    = blockIdx.x;
    const int warp = threadIdx.x >> 5;
    const int lane = threadIdx.x & 31;
    const int t0   = w * WTOK;
    const int rA   = 2 * warp + 1;       // tile row of this warp's token A (global t0+2*warp)
    const int rB   = 2 * warp + 2;       // token B

    // ---- Bulk load rows t0-1 .. t0+31 (w=0: rows t0..t0+31 into tile+1KB) ----
    const uint32_t mb = smem_u32(&mbar);
    if (threadIdx.x == 0) {
        asm volatile("mbarrier.init.shared::cta.b64 [%0], %1;" :: "r"(mb), "r"(1) : "memory");
    }
    __syncthreads();
    if (threadIdx.x == 0) {
        const uint32_t bytes = (w ? 33u : 32u) * 1024u;
        const float*   src   = x + (size_t)(w ? (t0 - 1) : 0) * 256;
        const uint32_t dst   = smem_u32(tile) + (w ? 0u : 1024u);
        asm volatile("mbarrier.arrive.expect_tx.shared::cta.b64 _, [%0], %1;"
                     :: "r"(mb), "r"(bytes) : "memory");
        asm volatile("cp.async.bulk.shared::cta.global.mbarrier::complete_tx::bytes [%0], [%1], %2, [%3];"
                     :: "r"(dst), "l"(src), "r"(bytes), "r"(mb) : "memory");
    }
    // all threads wait on phase 0
    asm volatile(
        "{\n\t.reg .pred P;\n\t"
        "W%=:\n\t"
        "mbarrier.try_wait.parity.acquire.cta.shared::cta.b64 P, [%0], 0;\n\t"
        "@P bra D%=;\n\t"
        "bra W%=;\n\t"
        "D%=:\n\t}"
        :: "r"(mb) : "memory");

    float4* t4 = (float4*)tile;
    if (w == 0 && warp == 0) {           // deterministic row 0 for the first window
        const float4 z = make_float4(0.f, 0.f, 0.f, 0.f);
        t4[lane] = z;  t4[32 + lane] = z;
    }

    // ---- Phase 1: norms of own rows (warp 0 also does row 0) ----
    const float4 a0 = t4[rA * 64 + lane], a1 = t4[rA * 64 + 32 + lane];
    const float4 b0 = t4[rB * 64 + lane], b1 = t4[rB * 64 + 32 + lane];
    {
        float sa = dot4(a0, a0) + dot4(a1, a1);
        float sb = dot4(b0, b0) + dot4(b1, b1);
        #pragma unroll
        for (int o = 16; o; o >>= 1) {
            sa += __shfl_xor_sync(0xFFFFFFFFu, sa, o);
            sb += __shfl_xor_sync(0xFFFFFFFFu, sb, o);
        }
        if (lane == 0) {
            inv_s[rA] = 1.0f / fmaxf(sqrtf(sa), 1e-12f);
            inv_s[rB] = 1.0f / fmaxf(sqrtf(sb), 1e-12f);
        }
        if (warp == 0) {
            float4 p0 = t4[lane], p1 = t4[32 + lane];
            float sp = warp_sum(dot4(p0, p0) + dot4(p1, p1));
            if (lane == 0) inv_s[0] = 1.0f / fmaxf(sqrtf(sp), 1e-12f);
        }
    }
    __syncthreads();

    const float invA = inv_s[rA];
    const float invB = inv_s[rB];

    // ---- Phase 2: adjacent dots (stage-3 masks) + weighted column sums ----
    bool m3A, m3B;
    {
        const float4 p0 = t4[(rA - 1) * 64 + lane], p1 = t4[(rA - 1) * 64 + 32 + lane];
        float dA = dot4(a0, p0) + dot4(a1, p1);
        float dB = dot4(b0, a0) + dot4(b1, a1);
        #pragma unroll
        for (int o = 16; o; o >>= 1) {
            dA += __shfl_xor_sync(0xFFFFFFFFu, dA, o);
            dB += __shfl_xor_sync(0xFFFFFFFFu, dB, o);
        }
        m3A = ((t0 + 2 * warp) == 0) || (invA * inv_s[rA - 1] * dA < 0.7f);
        m3B = (invB * invA * dB < 0.7f);
    }
    if (threadIdx.x < 256) {
        const int c = threadIdx.x;
        float acc = 0.0f;
        #pragma unroll
        for (int r = 1; r <= WTOK; r++) acc += tile[r * 256 + c] * inv_s[r];
        s_s[c] = acc;
    }
    __syncthreads();

    // ---- Phase 3: zero masked rows in place + mean-similarity dots ----
    {
        const float4 z = make_float4(0.f, 0.f, 0.f, 0.f);
        if (!m3A) { t4[rA * 64 + lane] = z;  t4[rA * 64 + 32 + lane] = z; }
        if (!m3B) { t4[rB * 64 + lane] = z;  t4[rB * 64 + 32 + lane] = z; }

        const float4* sv = (const float4*)s_s;
        const float4 s0 = sv[lane], s1 = sv[32 + lane];
        float dA = dot4(a0, s0) + dot4(a1, s1);
        float dB = dot4(b0, s0) + dot4(b1, s1);
        #pragma unroll
        for (int o = 16; o; o >>= 1) {
            dA += __shfl_xor_sync(0xFFFFFFFFu, dA, o);
            dB += __shfl_xor_sync(0xFFFFFFFFu, dB, o);
        }
        if (lane == 0) {
            ms_s[2 * warp]     = invA * dA * (1.0f / 32.0f);
            ms_s[2 * warp + 1] = invB * dB * (1.0f / 32.0f);
        }
    }
    __syncthreads();

    // ---- Phase 4: bulk store (warp 8, thread 256) || window stats (warp 0) ----
    if (threadIdx.x == 256) {
        asm volatile("fence.proxy.async.shared::cta;" ::: "memory");
        asm volatile("cp.async.bulk.global.shared::cta.bulk_group [%0], [%1], %2;"
                     :: "l"(comp_out + (size_t)t0 * 256),
                        "r"(smem_u32(tile) + 1024u),
                        "r"(32u * 1024u) : "memory");
        asm volatile("cp.async.bulk.commit_group;" ::: "memory");
    }
    if (warp == 0) {
        const float m = ms_s[lane];
        float mu = warp_sum(m) * (1.0f / 32.0f);
        float d = m - mu;
        float var = warp_sum(d * d) * (1.0f / 31.0f);   // ddof=1
        float sd = sqrtf(var);
        bool keep = !(m > mu + sd);
        unsigned bal = __ballot_sync(0xFFFFFFFFu, keep);
        if (bal == 0u) {
            // fallback: keep argmin(mean_sim), first index on ties
            float bv = m; int bi = lane;
            #pragma unroll
            for (int o = 16; o; o >>= 1) {
                float ov = __shfl_xor_sync(0xFFFFFFFFu, bv, o);
                int   oi = __shfl_xor_sync(0xFFFFFFFFu, bi, o);
                if (ov < bv || (ov == bv && oi < bi)) { bv = ov; bi = oi; }
            }
            keep = (lane == bi);
        }
        mask_out[t0 + lane] = keep ? 1.0f : 0.0f;
    }
    // ensure the bulk store's smem reads are done before the CTA retires
    if (threadIdx.x == 256) {
        asm volatile("cp.async.bulk.wait_group 0;" ::: "memory");
    }
}

extern "C" void kernel_launch(void* const* d_in, const int* in_sizes, int n_in,
                              void* d_out, int out_size)
{
    const float* x = (const float*)d_in[0];
    const int N = in_sizes[0] / 256;       // tokens
    const int nwin = N / WTOK;             // windows

    float* out = (float*)d_out;
    float* mask_out = out;                 // first N floats
    float* comp_out = out + N;             // N*256 floats, 16B aligned

    focus_kernel<<<nwin, 512>>>(x, mask_out, comp_out);
}

// round 6
// speedup vs baseline: 1.0769x; 1.0439x over previous
#include <cuda_runtime.h>
#include <cstdint>

// FocusModules, persistent double-buffered TMA pipeline.
// x: [N, 256] f32.  out (float32): [ mask1 (N) | compressed (N*256) ].
//
// Grid = 148*3 persistent CTAs (512 thr, 16 warps); each CTA loops over
// windows strided by gridDim. Per window: tile rows 0..32 = tokens t0-1..t0+31.
// mean_sim[i] = inv_i * dot(raw_i, s)/32, s[c] = sum_r raw[r][c]*inv_r.
// Double-buffered: load of window i+1 overlaps compute+store of window i.

#define WTOK 32
#define NCTA (148 * 3)

struct __align__(128) Smem {
    float tile[2][33 * 256];     // 2 x 33 KB
    float s_s[256];              // weighted column sums
    float inv_s[33];             // per-row 1/||x||
    float ms_s[WTOK];            // per-token mean similarity
    unsigned long long mbar[2];
};

__device__ __forceinline__ uint32_t smem_u32(const void* p) {
    return (uint32_t)__cvta_generic_to_shared(p);
}
__device__ __forceinline__ float warp_sum(float v) {
    #pragma unroll
    for (int o = 16; o; o >>= 1) v += __shfl_xor_sync(0xFFFFFFFFu, v, o);
    return v;
}
__device__ __forceinline__ float dot4(float4 a, float4 b) {
    return a.x * b.x + a.y * b.y + a.z * b.z + a.w * b.w;
}

__device__ __forceinline__ void issue_load(const float* __restrict__ x,
                                           Smem* sm, int w, int b) {
    const uint32_t bytes = (w ? 33u : 32u) * 1024u;
    const float*   src   = x + (size_t)(w ? (w * WTOK - 1) : 0) * 256;
    const uint32_t dst   = smem_u32(sm->tile[b]) + (w ? 0u : 1024u);
    const uint32_t mb    = smem_u32(&sm->mbar[b]);
    asm volatile("mbarrier.arrive.expect_tx.shared::cta.b64 _, [%0], %1;"
                 :: "r"(mb), "r"(bytes) : "memory");
    asm volatile("cp.async.bulk.shared::cta.global.mbarrier::complete_tx::bytes [%0], [%1], %2, [%3];"
                 :: "r"(dst), "l"(src), "r"(bytes), "r"(mb) : "memory");
}

__global__ void __launch_bounds__(512, 3)
focus_kernel(const float* __restrict__ x,
             float* __restrict__ mask_out,        // N floats (0/1)
             float* __restrict__ comp_out,        // N*256 floats
             int nwin)
{
    extern __shared__ __align__(128) char smem_raw[];
    Smem* sm = reinterpret_cast<Smem*>(smem_raw);

    const int warp = threadIdx.x >> 5;
    const int lane = threadIdx.x & 31;
    const int rA   = 2 * warp + 1;       // tile row of token t0+2*warp
    const int rB   = 2 * warp + 2;

    if (threadIdx.x == 0) {
        asm volatile("mbarrier.init.shared::cta.b64 [%0], %1;"
                     :: "r"(smem_u32(&sm->mbar[0])), "r"(1) : "memory");
        asm volatile("mbarrier.init.shared::cta.b64 [%0], %1;"
                     :: "r"(smem_u32(&sm->mbar[1])), "r"(1) : "memory");
        if ((int)blockIdx.x < nwin) issue_load(x, sm, blockIdx.x, 0);
    }
    __syncthreads();

    unsigned ph0 = 0, ph1 = 0;
    int it = 0;
    for (int w = blockIdx.x; w < nwin; w += NCTA, ++it) {
        const int b  = it & 1;
        const int t0 = w * WTOK;

        // Prefetch next window into the other buffer once its store has been
        // read out of smem.  (All compute reads of that buffer finished before
        // the store was issued, enforced by the pre-store __syncthreads.)
        if (threadIdx.x == 0) {
            const int wn = w + NCTA;
            if (wn < nwin) {
                asm volatile("cp.async.bulk.wait_group.read 0;" ::: "memory");
                issue_load(x, sm, wn, b ^ 1);
            }
        }

        // Wait for this buffer's load.
        {
            const uint32_t mb = smem_u32(&sm->mbar[b]);
            const unsigned ph = b ? ph1 : ph0;
            asm volatile(
                "{\n\t.reg .pred P;\n\t"
                "W%=:\n\t"
                "mbarrier.try_wait.parity.acquire.cta.shared::cta.b64 P, [%0], %1;\n\t"
                "@P bra D%=;\n\t"
                "bra W%=;\n\t"
                "D%=:\n\t}"
                :: "r"(mb), "r"(ph) : "memory");
            if (b) ph1 ^= 1u; else ph0 ^= 1u;
        }

        float4* t4 = (float4*)sm->tile[b];
        if (w == 0 && warp == 0) {       // deterministic row 0 for window 0
            const float4 z = make_float4(0.f, 0.f, 0.f, 0.f);
            t4[lane] = z;  t4[32 + lane] = z;
        }

        // ---- Phase 1: norms (warp 0 also does row 0) ----
        const float4 a0 = t4[rA * 64 + lane], a1 = t4[rA * 64 + 32 + lane];
        const float4 b0 = t4[rB * 64 + lane], b1 = t4[rB * 64 + 32 + lane];
        {
            float sa = dot4(a0, a0) + dot4(a1, a1);
            float sb = dot4(b0, b0) + dot4(b1, b1);
            #pragma unroll
            for (int o = 16; o; o >>= 1) {
                sa += __shfl_xor_sync(0xFFFFFFFFu, sa, o);
                sb += __shfl_xor_sync(0xFFFFFFFFu, sb, o);
            }
            if (lane == 0) {
                sm->inv_s[rA] = 1.0f / fmaxf(sqrtf(sa), 1e-12f);
                sm->inv_s[rB] = 1.0f / fmaxf(sqrtf(sb), 1e-12f);
            }
            if (warp == 0) {
                float4 p0 = t4[lane], p1 = t4[32 + lane];
                float sp = warp_sum(dot4(p0, p0) + dot4(p1, p1));
                if (lane == 0) sm->inv_s[0] = 1.0f / fmaxf(sqrtf(sp), 1e-12f);
            }
        }
        __syncthreads();

        const float invA = sm->inv_s[rA];
        const float invB = sm->inv_s[rB];

        // ---- Phase 2: adjacent dots (stage-3 masks) + weighted column sums ----
        bool m3A, m3B;
        {
            const float4 p0 = t4[(rA - 1) * 64 + lane];
            const float4 p1 = t4[(rA - 1) * 64 + 32 + lane];
            float dA = dot4(a0, p0) + dot4(a1, p1);
            float dB = dot4(b0, a0) + dot4(b1, a1);
            #pragma unroll
            for (int o = 16; o; o >>= 1) {
                dA += __shfl_xor_sync(0xFFFFFFFFu, dA, o);
                dB += __shfl_xor_sync(0xFFFFFFFFu, dB, o);
            }
            m3A = ((t0 + 2 * warp) == 0) || (invA * sm->inv_s[rA - 1] * dA < 0.7f);
            m3B = (invB * invA * dB < 0.7f);
        }
        if (threadIdx.x < 256) {
            const float* tb = sm->tile[b];
            const int c = threadIdx.x;
            float acc = 0.0f;
            #pragma unroll
            for (int r = 1; r <= WTOK; r++) acc += tb[r * 256 + c] * sm->inv_s[r];
            sm->s_s[c] = acc;
        }
        __syncthreads();

        // ---- Phase 3: zero masked rows in place + mean-similarity dots ----
        {
            const float4 z = make_float4(0.f, 0.f, 0.f, 0.f);
            if (!m3A) { t4[rA * 64 + lane] = z;  t4[rA * 64 + 32 + lane] = z; }
            if (!m3B) { t4[rB * 64 + lane] = z;  t4[rB * 64 + 32 + lane] = z; }

            const float4* sv = (const float4*)sm->s_s;
            const float4 s0 = sv[lane], s1 = sv[32 + lane];
            float dA = dot4(a0, s0) + dot4(a1, s1);
            float dB = dot4(b0, s0) + dot4(b1, s1);
            #pragma unroll
            for (int o = 16; o; o >>= 1) {
                dA += __shfl_xor_sync(0xFFFFFFFFu, dA, o);
                dB += __shfl_xor_sync(0xFFFFFFFFu, dB, o);
            }
            if (lane == 0) {
                sm->ms_s[2 * warp]     = invA * dA * (1.0f / 32.0f);
                sm->ms_s[2 * warp + 1] = invB * dB * (1.0f / 32.0f);
            }
        }
        __syncthreads();

        // ---- Phase 4: bulk store (thread 0) || window stats (warp 0) ----
        if (threadIdx.x == 0) {
            asm volatile("fence.proxy.async.shared::cta;" ::: "memory");
            asm volatile("cp.async.bulk.global.shared::cta.bulk_group [%0], [%1], %2;"
                         :: "l"(comp_out + (size_t)t0 * 256),
                            "r"(smem_u32(sm->tile[b]) + 1024u),
                            "r"(32u * 1024u) : "memory");
            asm volatile("cp.async.bulk.commit_group;" ::: "memory");
        }
        if (warp == 0) {
            const float m = sm->ms_s[lane];
            float mu = warp_sum(m) * (1.0f / 32.0f);
            float d = m - mu;
            float var = warp_sum(d * d) * (1.0f / 31.0f);   // ddof=1
            float sd = sqrtf(var);
            bool keep = !(m > mu + sd);
            unsigned bal = __ballot_sync(0xFFFFFFFFu, keep);
            if (bal == 0u) {
                // fallback: keep argmin(mean_sim), first index on ties
                float bv = m; int bi = lane;
                #pragma unroll
                for (int o = 16; o; o >>= 1) {
                    float ov = __shfl_xor_sync(0xFFFFFFFFu, bv, o);
                    int   oi = __shfl_xor_sync(0xFFFFFFFFu, bi, o);
                    if (ov < bv || (ov == bv && oi < bi)) { bv = ov; bi = oi; }
                }
                keep = (lane == bi);
            }
            mask_out[t0 + lane] = keep ? 1.0f : 0.0f;
        }
    }

    // drain outstanding bulk stores before CTA exit
    if (threadIdx.x == 0) {
        asm volatile("cp.async.bulk.wait_group 0;" ::: "memory");
    }
}

extern "C" void kernel_launch(void* const* d_in, const int* in_sizes, int n_in,
                              void* d_out, int out_size)
{
    const float* x = (const float*)d_in[0];
    const int N = in_sizes[0] / 256;       // tokens
    const int nwin = N / WTOK;             // windows

    float* out = (float*)d_out;
    float* mask_out = out;                 // first N floats
    float* comp_out = out + N;             // N*256 floats

    cudaFuncSetAttribute(focus_kernel,
                         cudaFuncAttributeMaxDynamicSharedMemorySize,
                         (int)sizeof(Smem));
    focus_kernel<<<NCTA, 512, sizeof(Smem)>>>(x, mask_out, comp_out, nwin);
}